// round 4
// baseline (speedup 1.0000x reference)
#include <cuda_runtime.h>
#include <math.h>

#define BATCH   256
#define NNODE   128
#define NTOT    32768
#define NEDGE   262144
#define FDIM    128
#define LDIMS   61
#define LMAT    16384
#define SK_ITERS 6
#define APAD    132
#define SMEM_AW  ((128*APAD + 128*128)*4)
#define SMEM_ABT ((128*APAD + 128*APAD)*4)

struct Scratch {
    float feat1[NTOT*FDIM]; float feat2[NTOT*FDIM];
    float f11[NTOT*FDIM]; float f12[NTOT*FDIM]; float f13[NTOT*FDIM];
    float f21[NTOT*FDIM]; float f22[NTOT*FDIM]; float f23[NTOT*FDIM];
    float htmp[NTOT*FDIM];
    float aff[BATCH*LMAT];
    float cw1[NEDGE]; float cw2[NEDGE];
    float dinv1[NTOT]; float dinv2[NTOT];
    float scores[BATCH*1024];
    int csrc1[NEDGE]; int csrc2[NEDGE];
    int deg1[NTOT]; int deg2[NTOT];
    int fill1[NTOT]; int fill2[NTOT];
    int rp1[NTOT+1]; int rp2[NTOT+1];
};
__device__ Scratch g_scratch;

// FMA-pipe sigmoid (no MUFU): exp via range reduction + deg-5 poly, recip via Newton.
__device__ __forceinline__ float fast_sigmoid(float z) {
    float az = fminf(fabsf(z), 80.0f);
    float t = az * 1.4426950408889634f;
    float n = rintf(t);
    float w = -(t - n) * 0.6931471805599453f;
    float p = fmaf(w, 0.00833333377f, 0.0416666679f);
    p = fmaf(w, p, 0.16666667f);
    p = fmaf(w, p, 0.5f);
    p = fmaf(w, p, 1.0f);
    p = fmaf(w, p, 1.0f);
    float e = p * __int_as_float((127 - (int)n) << 23);  // exp(-az)
    float d = 1.0f + e;
    float y = fmaf(-0.5f, d, 1.45711f);
    y = y * fmaf(-d, y, 2.0f);
    y = y * fmaf(-d, y, 2.0f);
    y = y * fmaf(-d, y, 2.0f);
    return (z >= 0.0f) ? y : e * y;
}

__global__ void zero4_kernel(int* a, int* b, int* c, int* d) {
    int i = blockIdx.x*blockDim.x + threadIdx.x;
    if (i < NTOT) { a[i]=0; b[i]=0; c[i]=0; d[i]=0; }
}
__global__ void count_kernel(const int* __restrict__ dst, int* __restrict__ deg) {
    int e = blockIdx.x*blockDim.x + threadIdx.x;
    if (e < NEDGE) atomicAdd(&deg[dst[e]], 1);
}
__global__ void dinv_kernel(const int* __restrict__ deg, float* __restrict__ dinv) {
    int n = blockIdx.x*blockDim.x + threadIdx.x;
    if (n < NTOT) dinv[n] = rsqrtf((float)(deg[n] + 1));
}
__global__ void scan_kernel(const int* __restrict__ deg, int* __restrict__ rp) {
    __shared__ int s[1024];
    int tid = threadIdx.x;
    int carry = 0;
    for (int c = 0; c < 32; ++c) {
        int i = c*1024 + tid;
        int v = deg[i];
        s[tid] = v;
        __syncthreads();
        for (int off = 1; off < 1024; off <<= 1) {
            int t = (tid >= off) ? s[tid-off] : 0;
            __syncthreads();
            s[tid] += t;
            __syncthreads();
        }
        rp[i] = carry + s[tid] - v;
        carry += s[1023];
        __syncthreads();
    }
    if (tid == 0) rp[NTOT] = carry;
}
__global__ void scatter_kernel(const int* __restrict__ src, const int* __restrict__ dst,
                               const int* __restrict__ rp, int* __restrict__ fill,
                               const float* __restrict__ dinv,
                               int* __restrict__ csrc, float* __restrict__ cw) {
    int e = blockIdx.x*blockDim.x + threadIdx.x;
    if (e >= NEDGE) return;
    int s = src[e], d = dst[e];
    int pos = rp[d] + atomicAdd(&fill[d], 1);
    csrc[pos] = s;
    cw[pos] = dinv[s] * dinv[d];
}

__global__ void init_feat_kernel(const float* __restrict__ x, const int* __restrict__ cent,
                                 const float* __restrict__ rw, const float* __restrict__ emb,
                                 const float* __restrict__ W, const float* __restrict__ bias,
                                 float* __restrict__ out) {
    int half = threadIdx.x >> 7;
    int f = threadIdx.x & 127;
    int node = blockIdx.x*2 + half;
    __shared__ float a[2][LDIMS];
    if (f < 29)      a[half][f] = x[node*29 + f];
    else if (f < 45) a[half][f] = emb[cent[node]*16 + (f-29)];
    else if (f < 61) a[half][f] = rw[node*16 + (f-45)];
    __syncthreads();
    float acc = bias[f];
    #pragma unroll
    for (int c = 0; c < LDIMS; ++c)
        acc = fmaf(a[half][c], W[c*FDIM + f], acc);
    out[((size_t)node << 7) + f] = fmaxf(acc, 0.0f);
}

// C[M,128] = op(A)[M,128] @ W[128,128]
__global__ void __launch_bounds__(256, 1)
gemm_aw_kernel(const float* __restrict__ A, const float* __restrict__ W,
               float* __restrict__ C, int relu_a) {
    extern __shared__ float sm[];
    float* As = sm;               // [128][APAD] transposed: As[k][m]
    float* Bs = sm + 128*APAD;    // [128][128]  Bs[k][n]
    int tid = threadIdx.x;
    size_t m0 = (size_t)blockIdx.x * 128;
    int lr = tid >> 5, lc = (tid & 31) << 2;
    #pragma unroll
    for (int it = 0; it < 16; ++it) {
        int m = (it << 3) + lr;
        float4 v = *(const float4*)(A + (m0 + m)*FDIM + lc);
        if (relu_a) { v.x=fmaxf(v.x,0.f); v.y=fmaxf(v.y,0.f); v.z=fmaxf(v.z,0.f); v.w=fmaxf(v.w,0.f); }
        As[(lc+0)*APAD + m] = v.x; As[(lc+1)*APAD + m] = v.y;
        As[(lc+2)*APAD + m] = v.z; As[(lc+3)*APAD + m] = v.w;
        *(float4*)(Bs + m*128 + lc) = *(const float4*)(W + m*FDIM + lc);
    }
    __syncthreads();
    int tx = tid & 15, ty = tid >> 4;
    float acc[8][8];
    #pragma unroll
    for (int i = 0; i < 8; ++i)
        #pragma unroll
        for (int j = 0; j < 8; ++j) acc[i][j] = 0.0f;
    #pragma unroll 8
    for (int k = 0; k < 128; ++k) {
        float4 a0 = *(float4*)(As + k*APAD + (ty<<2));
        float4 a1 = *(float4*)(As + k*APAD + 64 + (ty<<2));
        float4 b0 = *(float4*)(Bs + k*128 + (tx<<2));
        float4 b1 = *(float4*)(Bs + k*128 + 64 + (tx<<2));
        float av[8] = {a0.x,a0.y,a0.z,a0.w,a1.x,a1.y,a1.z,a1.w};
        float bv[8] = {b0.x,b0.y,b0.z,b0.w,b1.x,b1.y,b1.z,b1.w};
        #pragma unroll
        for (int i = 0; i < 8; ++i)
            #pragma unroll
            for (int j = 0; j < 8; ++j)
                acc[i][j] = fmaf(av[i], bv[j], acc[i][j]);
    }
    #pragma unroll
    for (int i = 0; i < 8; ++i) {
        int row = (i < 4) ? ((ty<<2)+i) : (64+(ty<<2)+(i-4));
        float* cp = C + (m0 + row)*FDIM;
        float4 o0 = {acc[i][0],acc[i][1],acc[i][2],acc[i][3]};
        float4 o1 = {acc[i][4],acc[i][5],acc[i][6],acc[i][7]};
        *(float4*)(cp + (tx<<2)) = o0;
        *(float4*)(cp + 64 + (tx<<2)) = o1;
    }
}

// Per-graph: C[b] = A[b](128x128) @ B[b]^T
__global__ void __launch_bounds__(256, 1)
gemm_abt_kernel(const float* __restrict__ Aall, const float* __restrict__ Ball,
                float* __restrict__ Call) {
    extern __shared__ float sm[];
    float* As = sm;
    float* Bs = sm + 128*APAD;
    int tid = threadIdx.x;
    size_t base = (size_t)blockIdx.x * LMAT;
    const float* A = Aall + base;
    const float* B = Ball + base;
    float* C = Call + base;
    int lr = tid >> 5, lc = (tid & 31) << 2;
    #pragma unroll
    for (int it = 0; it < 16; ++it) {
        int m = (it << 3) + lr;
        float4 va = *(const float4*)(A + m*128 + lc);
        As[(lc+0)*APAD + m] = va.x; As[(lc+1)*APAD + m] = va.y;
        As[(lc+2)*APAD + m] = va.z; As[(lc+3)*APAD + m] = va.w;
        float4 vb = *(const float4*)(B + m*128 + lc);
        Bs[(lc+0)*APAD + m] = vb.x; Bs[(lc+1)*APAD + m] = vb.y;
        Bs[(lc+2)*APAD + m] = vb.z; Bs[(lc+3)*APAD + m] = vb.w;
    }
    __syncthreads();
    int tx = tid & 15, ty = tid >> 4;
    float acc[8][8];
    #pragma unroll
    for (int i = 0; i < 8; ++i)
        #pragma unroll
        for (int j = 0; j < 8; ++j) acc[i][j] = 0.0f;
    #pragma unroll 8
    for (int k = 0; k < 128; ++k) {
        float4 a0 = *(float4*)(As + k*APAD + (ty<<2));
        float4 a1 = *(float4*)(As + k*APAD + 64 + (ty<<2));
        float4 b0 = *(float4*)(Bs + k*APAD + (tx<<2));
        float4 b1 = *(float4*)(Bs + k*APAD + 64 + (tx<<2));
        float av[8] = {a0.x,a0.y,a0.z,a0.w,a1.x,a1.y,a1.z,a1.w};
        float bv[8] = {b0.x,b0.y,b0.z,b0.w,b1.x,b1.y,b1.z,b1.w};
        #pragma unroll
        for (int i = 0; i < 8; ++i)
            #pragma unroll
            for (int j = 0; j < 8; ++j)
                acc[i][j] = fmaf(av[i], bv[j], acc[i][j]);
    }
    #pragma unroll
    for (int i = 0; i < 8; ++i) {
        int row = (i < 4) ? ((ty<<2)+i) : (64+(ty<<2)+(i-4));
        float* cp = C + row*128;
        float4 o0 = {acc[i][0],acc[i][1],acc[i][2],acc[i][3]};
        float4 o1 = {acc[i][4],acc[i][5],acc[i][6],acc[i][7]};
        *(float4*)(cp + (tx<<2)) = o0;
        *(float4*)(cp + 64 + (tx<<2)) = o1;
    }
}

// out[n][f] = h[n][f]*dinv[n]^2 + bias[f] + sum_edges h[src][f]*w
__global__ void agg_kernel(const float* __restrict__ h, const float* __restrict__ bias,
                           const int* __restrict__ rp, const int* __restrict__ csrc,
                           const float* __restrict__ cw, const float* __restrict__ dinv,
                           float* __restrict__ out) {
    int n = blockIdx.x;
    int f = threadIdx.x;
    float di = dinv[n];
    float acc = fmaf(h[((size_t)n << 7) + f], di*di, bias[f]);
    int e = rp[n], e1 = rp[n+1];
    for (; e + 4 <= e1; e += 4) {
        int s0 = csrc[e], s1 = csrc[e+1], s2 = csrc[e+2], s3 = csrc[e+3];
        float w0 = cw[e], w1 = cw[e+1], w2 = cw[e+2], w3 = cw[e+3];
        acc = fmaf(h[((size_t)s0<<7)+f], w0, acc);
        acc = fmaf(h[((size_t)s1<<7)+f], w1, acc);
        acc = fmaf(h[((size_t)s2<<7)+f], w2, acc);
        acc = fmaf(h[((size_t)s3<<7)+f], w3, acc);
    }
    for (; e < e1; ++e)
        acc = fmaf(h[((size_t)csrc[e]<<7)+f], cw[e], acc);
    out[((size_t)n << 7) + f] = acc;
}

// 2-anchor Sinkhorn closed form: prob = (k/T6) * sigmoid(2x - (min+max) + d5)
__global__ void sinkhorn_kernel(const float* __restrict__ aff, const int* __restrict__ topk,
                                float* __restrict__ out) {
    extern __shared__ float xs[];
    __shared__ float rmn[8], rmx[8], rbuf[8], bc[2];
    int tid = threadIdx.x;            // 256
    int lane = tid & 31, wid = tid >> 5;
    size_t base = (size_t)blockIdx.x * LMAT;
    const float* x = aff + base;
    float* P = out + base;

    float mn = 3.4e38f, mx = -3.4e38f;
    for (int i = tid; i < LMAT; i += 256) {
        float v = x[i];
        xs[i] = v;
        mn = fminf(mn, v); mx = fmaxf(mx, v);
    }
    #pragma unroll
    for (int off = 16; off; off >>= 1) {
        mn = fminf(mn, __shfl_xor_sync(0xffffffffu, mn, off));
        mx = fmaxf(mx, __shfl_xor_sync(0xffffffffu, mx, off));
    }
    if (lane == 0) { rmn[wid] = mn; rmx[wid] = mx; }
    __syncthreads();
    if (tid == 0) {
        float m1 = rmn[0], m2 = rmx[0];
        for (int w = 1; w < 8; ++w) { m1 = fminf(m1, rmn[w]); m2 = fmaxf(m2, rmx[w]); }
        bc[0] = m1 + m2;              // min+max (the +-1 anchor offsets cancel)
    }
    __syncthreads();
    float Cc = bc[0];
    float kf = 0.5f * (float)(*topk);
    const float Lf = (float)LMAT;
    float lk = logf(kf / (Lf - kf));
    float delta = 0.0f, scale = 0.0f;

    for (int it = 0; it < SK_ITERS; ++it) {
        float T = 0.0f;
        for (int i = tid; i < LMAT; i += 256)
            T += fast_sigmoid(fmaf(2.0f, xs[i], delta - Cc));
        #pragma unroll
        for (int off = 16; off; off >>= 1)
            T += __shfl_xor_sync(0xffffffffu, T, off);
        if (lane == 0) rbuf[wid] = T;
        __syncthreads();
        if (tid == 0) {
            float s = 0.0f;
            for (int w = 0; w < 8; ++w) s += rbuf[w];
            bc[1] = s;
        }
        __syncthreads();
        float Tall = bc[1];
        if (it < SK_ITERS - 1) delta += lk + logf((Lf - Tall) / Tall);
        else scale = kf / Tall;
        __syncthreads();
    }
    for (int i = tid; i < LMAT; i += 256)
        P[i] = scale * fast_sigmoid(fmaf(2.0f, xs[i], delta - Cc));
}

__global__ void gf_kernel(const float* __restrict__ a0, const float* __restrict__ a1,
                          const float* __restrict__ a2, const float* __restrict__ a3,
                          const float* __restrict__ b0, const float* __restrict__ b1,
                          const float* __restrict__ b2, const float* __restrict__ b3,
                          float* __restrict__ scores) {
    int b = blockIdx.x;
    int d = threadIdx.x;              // 512
    int which = d >> 7, f = d & 127;
    const float* p1 = (which==0?a0:which==1?a1:which==2?a2:a3) + (((size_t)b*NNODE)<<7) + f;
    float s = 0.0f;
    #pragma unroll 4
    for (int n = 0; n < NNODE; ++n) s += p1[n<<7];
    scores[b*1024 + d] = s;
    const float* p2 = (which==0?b0:which==1?b1:which==2?b2:b3) + (((size_t)b*NNODE)<<7) + f;
    float m = -3.4e38f;
    #pragma unroll 4
    for (int n = 0; n < NNODE; ++n) m = fmaxf(m, p2[n<<7]);
    scores[b*1024 + 512 + d] = m;
}

__global__ void score_kernel(const float* __restrict__ scores,
                             const float* __restrict__ W1, const float* __restrict__ b1,
                             const float* __restrict__ W2, const float* __restrict__ b2,
                             float* __restrict__ ged) {
    int b = blockIdx.x;
    int j = threadIdx.x;              // 64
    __shared__ float sv[1024];
    __shared__ float rr[2];
    for (int i = j; i < 1024; i += 64) sv[i] = scores[b*1024 + i];
    __syncthreads();
    float acc = b1[j];
    #pragma unroll 8
    for (int i = 0; i < 1024; ++i)
        acc = fmaf(sv[i], W1[i*64 + j], acc);
    float pv = fmaxf(acc, 0.0f) * W2[j];
    #pragma unroll
    for (int off = 16; off; off >>= 1)
        pv += __shfl_xor_sync(0xffffffffu, pv, off);
    if ((j & 31) == 0) rr[j >> 5] = pv;
    __syncthreads();
    if (j == 0) {
        float v = rr[0] + rr[1] + b2[0];
        ged[b] = 1.0f / (1.0f + expf(-v));
    }
}

extern "C" void kernel_launch(void* const* d_in, const int* in_sizes, int n_in,
                              void* d_out, int out_size) {
    const float* x1    = (const float*)d_in[0];
    const int*   cent1 = (const int*)d_in[1];
    const float* rw1   = (const float*)d_in[2];
    const int*   src1  = (const int*)d_in[3];
    const int*   dst1  = (const int*)d_in[4];
    const float* x2    = (const float*)d_in[5];
    const int*   cent2 = (const int*)d_in[6];
    const float* rw2   = (const float*)d_in[7];
    const int*   src2  = (const int*)d_in[8];
    const int*   dst2  = (const int*)d_in[9];
    const float* emb   = (const float*)d_in[10];
    const float* initW = (const float*)d_in[11];
    const float* initb = (const float*)d_in[12];
    const float* W1    = (const float*)d_in[13];
    const float* b1    = (const float*)d_in[14];
    const float* W2    = (const float*)d_in[15];
    const float* b2    = (const float*)d_in[16];
    const float* W3    = (const float*)d_in[17];
    const float* b3    = (const float*)d_in[18];
    const float* Aaff  = (const float*)d_in[19];
    const float* scW1  = (const float*)d_in[20];
    const float* scb1  = (const float*)d_in[21];
    const float* scW2  = (const float*)d_in[22];
    const float* scb2  = (const float*)d_in[23];
    const int*   topk  = (const int*)d_in[24];

    Scratch* S = nullptr;
    cudaGetSymbolAddress((void**)&S, g_scratch);

    float* out  = (float*)d_out;
    float* ged  = out;
    float* sim1 = out + BATCH;
    float* sim2 = out + BATCH + (size_t)BATCH * LMAT;

    cudaFuncSetAttribute(gemm_aw_kernel,  cudaFuncAttributeMaxDynamicSharedMemorySize, SMEM_AW);
    cudaFuncSetAttribute(gemm_abt_kernel, cudaFuncAttributeMaxDynamicSharedMemorySize, SMEM_ABT);
    cudaFuncSetAttribute(sinkhorn_kernel, cudaFuncAttributeMaxDynamicSharedMemorySize, LMAT*4);

    // CSR build (both graphs)
    zero4_kernel<<<128, 256>>>(S->deg1, S->deg2, S->fill1, S->fill2);
    count_kernel<<<1024, 256>>>(dst1, S->deg1);
    count_kernel<<<1024, 256>>>(dst2, S->deg2);
    dinv_kernel<<<128, 256>>>(S->deg1, S->dinv1);
    dinv_kernel<<<128, 256>>>(S->deg2, S->dinv2);
    scan_kernel<<<1, 1024>>>(S->deg1, S->rp1);
    scan_kernel<<<1, 1024>>>(S->deg2, S->rp2);
    scatter_kernel<<<1024, 256>>>(src1, dst1, S->rp1, S->fill1, S->dinv1, S->csrc1, S->cw1);
    scatter_kernel<<<1024, 256>>>(src2, dst2, S->rp2, S->fill2, S->dinv2, S->csrc2, S->cw2);

    // Initial features
    init_feat_kernel<<<NTOT/2, 256>>>(x1, cent1, rw1, emb, initW, initb, S->feat1);
    init_feat_kernel<<<NTOT/2, 256>>>(x2, cent2, rw2, emb, initW, initb, S->feat2);

    // GCN conv pass, graph 1
    gemm_aw_kernel<<<NTOT/128, 256, SMEM_AW>>>(S->feat1, W1, S->htmp, 0);
    agg_kernel<<<NTOT, 128>>>(S->htmp, b1, S->rp1, S->csrc1, S->cw1, S->dinv1, S->f11);
    gemm_aw_kernel<<<NTOT/128, 256, SMEM_AW>>>(S->f11, W2, S->htmp, 1);
    agg_kernel<<<NTOT, 128>>>(S->htmp, b2, S->rp1, S->csrc1, S->cw1, S->dinv1, S->f12);
    gemm_aw_kernel<<<NTOT/128, 256, SMEM_AW>>>(S->f12, W3, S->htmp, 1);
    agg_kernel<<<NTOT, 128>>>(S->htmp, b3, S->rp1, S->csrc1, S->cw1, S->dinv1, S->f13);

    // GCN conv pass, graph 2
    gemm_aw_kernel<<<NTOT/128, 256, SMEM_AW>>>(S->feat2, W1, S->htmp, 0);
    agg_kernel<<<NTOT, 128>>>(S->htmp, b1, S->rp2, S->csrc2, S->cw2, S->dinv2, S->f21);
    gemm_aw_kernel<<<NTOT/128, 256, SMEM_AW>>>(S->f21, W2, S->htmp, 1);
    agg_kernel<<<NTOT, 128>>>(S->htmp, b2, S->rp2, S->csrc2, S->cw2, S->dinv2, S->f22);
    gemm_aw_kernel<<<NTOT/128, 256, SMEM_AW>>>(S->f22, W3, S->htmp, 1);
    agg_kernel<<<NTOT, 128>>>(S->htmp, b3, S->rp2, S->csrc2, S->cw2, S->dinv2, S->f23);

    // sim1: affinity(feat1, feat2) -> sinkhorn
    gemm_aw_kernel<<<NTOT/128, 256, SMEM_AW>>>(S->feat1, Aaff, S->htmp, 0);
    gemm_abt_kernel<<<BATCH, 256, SMEM_ABT>>>(S->htmp, S->feat2, S->aff);
    sinkhorn_kernel<<<BATCH, 256, LMAT*4>>>(S->aff, topk, sim1);

    // sim2: affinity(f13, f23) -> sinkhorn
    gemm_aw_kernel<<<NTOT/128, 256, SMEM_AW>>>(S->f13, Aaff, S->htmp, 0);
    gemm_abt_kernel<<<BATCH, 256, SMEM_ABT>>>(S->htmp, S->f23, S->aff);
    sinkhorn_kernel<<<BATCH, 256, LMAT*4>>>(S->aff, topk, sim2);

    // Graph features + scorer MLP
    gf_kernel<<<BATCH, 512>>>(S->feat1, S->f11, S->f12, S->f13,
                              S->feat2, S->f21, S->f22, S->f23, S->scores);
    score_kernel<<<BATCH, 64>>>(S->scores, scW1, scb1, scW2, scb2, ged);
}

// round 5
// speedup vs baseline: 1.1310x; 1.1310x over previous
#include <cuda_runtime.h>
#include <math.h>

#define BATCH   256
#define NNODE   128
#define NTOT    32768
#define NTOT2   65536
#define NEDGE   262144
#define NEDGE2  524288
#define FDIM    128
#define HALF    (NTOT*FDIM)
#define LDIMS   61
#define LMAT    16384
#define SK_ITERS 6
#define APAD    132
#define SMEM_AW   ((128*APAD + 128*128)*4)
#define SMEM_FUSE ((128*APAD + 128*128 + 128*APAD)*4)

typedef unsigned long long u64;

struct Scratch {
    float feat[NTOT2*FDIM];
    float fa[NTOT2*FDIM];
    float fb[NTOT2*FDIM];
    float fc[NTOT2*FDIM];
    float htmp[NTOT2*FDIM];
    float cw[NEDGE2];
    float dinv[NTOT2];
    float scores[BATCH*1024];
    int csrc[NEDGE2];
    int deg[NTOT2];
    int fill[NTOT2];
    int rp[NTOT2+1];
    int bsum[64];
};
__device__ Scratch g_scratch;

// ---------------- f32x2 packed FMA helpers (2x fp32 throughput) ----------------
__device__ __forceinline__ u64 pack2(float v) {
    u64 r; asm("mov.b64 %0, {%1, %1};" : "=l"(r) : "f"(v)); return r;
}
__device__ __forceinline__ void ffma2(u64& d, u64 a, u64 b) {
    asm("fma.rn.f32x2 %0, %1, %2, %3;" : "=l"(d) : "l"(a), "l"(b), "l"(d));
}
__device__ __forceinline__ float2 unpack2(u64 v) {
    float2 f; asm("mov.b64 {%0, %1}, %2;" : "=f"(f.x), "=f"(f.y) : "l"(v)); return f;
}

// FMA-pipe sigmoid (no MUFU)
__device__ __forceinline__ float fast_sigmoid(float z) {
    float az = fminf(fabsf(z), 80.0f);
    float t = az * 1.4426950408889634f;
    float n = rintf(t);
    float w = -(t - n) * 0.6931471805599453f;
    float p = fmaf(w, 0.00833333377f, 0.0416666679f);
    p = fmaf(w, p, 0.16666667f);
    p = fmaf(w, p, 0.5f);
    p = fmaf(w, p, 1.0f);
    p = fmaf(w, p, 1.0f);
    float e = p * __int_as_float((127 - (int)n) << 23);
    float d = 1.0f + e;
    float y = fmaf(-0.5f, d, 1.45711f);
    y = y * fmaf(-d, y, 2.0f);
    y = y * fmaf(-d, y, 2.0f);
    y = y * fmaf(-d, y, 2.0f);
    return (z >= 0.0f) ? y : e * y;
}

// ---------------- CSR build (combined 2-graph node space) ----------------
__global__ void count_kernel(const int* __restrict__ dst1, const int* __restrict__ dst2,
                             int* __restrict__ deg) {
    int e = blockIdx.x*blockDim.x + threadIdx.x;
    if (e < NEDGE) atomicAdd(&deg[dst1[e]], 1);
    else if (e < NEDGE2) atomicAdd(&deg[dst2[e - NEDGE] + NTOT], 1);
}
__global__ void dinv_kernel(const int* __restrict__ deg, float* __restrict__ dinv) {
    int n = blockIdx.x*blockDim.x + threadIdx.x;
    if (n < NTOT2) dinv[n] = rsqrtf((float)(deg[n] + 1));
}

// hierarchical exclusive scan of 65536 ints: 64 blocks x 1024
__global__ void scan_block_kernel(const int* __restrict__ deg, int* __restrict__ rp,
                                  int* __restrict__ bsum) {
    __shared__ int ws[32];
    int tid = threadIdx.x, lane = tid & 31, wid = tid >> 5;
    int gi = blockIdx.x*1024 + tid;
    int v = deg[gi];
    int x = v;
    #pragma unroll
    for (int off = 1; off < 32; off <<= 1) {
        int t = __shfl_up_sync(0xffffffffu, x, off);
        if (lane >= off) x += t;
    }
    if (lane == 31) ws[wid] = x;
    __syncthreads();
    if (wid == 0) {
        int y = ws[lane];
        #pragma unroll
        for (int off = 1; off < 32; off <<= 1) {
            int t = __shfl_up_sync(0xffffffffu, y, off);
            if (lane >= off) y += t;
        }
        ws[lane] = y;
    }
    __syncthreads();
    int woff = (wid > 0) ? ws[wid-1] : 0;
    rp[gi] = woff + x - v;
    if (tid == 1023) bsum[blockIdx.x] = woff + x;
}
__global__ void scan_top_kernel(int* __restrict__ bsum) {
    __shared__ int s[64];
    int tid = threadIdx.x;           // 64
    s[tid] = bsum[tid];
    __syncthreads();
    if (tid == 0) {
        int acc = 0;
        for (int i = 0; i < 64; ++i) { int v = s[i]; s[i] = acc; acc += v; }
    }
    __syncthreads();
    bsum[tid] = s[tid];
}
__global__ void scan_add_kernel(int* __restrict__ rp, const int* __restrict__ bsum) {
    int gi = blockIdx.x*1024 + threadIdx.x;
    rp[gi] += bsum[blockIdx.x];
    if (gi == 0) rp[NTOT2] = NEDGE2;
}
__global__ void scatter_kernel(const int* __restrict__ src1, const int* __restrict__ dst1,
                               const int* __restrict__ src2, const int* __restrict__ dst2,
                               const int* __restrict__ rp, int* __restrict__ fill,
                               const float* __restrict__ dinv,
                               int* __restrict__ csrc, float* __restrict__ cw) {
    int e = blockIdx.x*blockDim.x + threadIdx.x;
    if (e >= NEDGE2) return;
    int s, d;
    if (e < NEDGE) { s = src1[e]; d = dst1[e]; }
    else { s = src2[e - NEDGE] + NTOT; d = dst2[e - NEDGE] + NTOT; }
    int pos = rp[d] + atomicAdd(&fill[d], 1);
    csrc[pos] = s;
    cw[pos] = dinv[s] * dinv[d];
}

// ---------------- initial features (both graphs, one launch) ----------------
__global__ void init_feat_kernel(const float* __restrict__ x1, const int* __restrict__ c1,
                                 const float* __restrict__ rw1,
                                 const float* __restrict__ x2, const int* __restrict__ c2,
                                 const float* __restrict__ rw2,
                                 const float* __restrict__ emb,
                                 const float* __restrict__ W, const float* __restrict__ bias,
                                 float* __restrict__ out) {
    int which = blockIdx.x >> 14;               // 16384 blocks per graph
    int bi = blockIdx.x & 16383;
    const float* x  = which ? x2 : x1;
    const int*   ce = which ? c2 : c1;
    const float* rw = which ? rw2 : rw1;
    int half = threadIdx.x >> 7;
    int f = threadIdx.x & 127;
    int node = bi*2 + half;
    __shared__ float a[2][LDIMS];
    if (f < 29)      a[half][f] = x[node*29 + f];
    else if (f < 45) a[half][f] = emb[ce[node]*16 + (f-29)];
    else if (f < 61) a[half][f] = rw[node*16 + (f-45)];
    __syncthreads();
    float acc = bias[f];
    #pragma unroll
    for (int c = 0; c < LDIMS; ++c)
        acc = fmaf(a[half][c], W[c*FDIM + f], acc);
    out[((size_t)(which*NTOT + node) << 7) + f] = fmaxf(acc, 0.0f);
}

// ---------------- GEMM C[M,128] = op(A)[M,128] @ W[128,128], f32x2 ----------------
__global__ void __launch_bounds__(256, 1)
gemm_aw_kernel(const float* __restrict__ A, const float* __restrict__ W,
               float* __restrict__ C, int relu_a) {
    extern __shared__ float sm[];
    float* As = sm;               // [128][APAD] transposed: As[k][m]
    float* Bs = sm + 128*APAD;    // [128][128]  Bs[k][n]
    int tid = threadIdx.x;
    size_t m0 = (size_t)blockIdx.x * 128;
    int lr = tid >> 5, lc = (tid & 31) << 2;
    #pragma unroll
    for (int it = 0; it < 16; ++it) {
        int m = (it << 3) + lr;
        float4 v = *(const float4*)(A + (m0 + m)*FDIM + lc);
        if (relu_a) { v.x=fmaxf(v.x,0.f); v.y=fmaxf(v.y,0.f); v.z=fmaxf(v.z,0.f); v.w=fmaxf(v.w,0.f); }
        As[(lc+0)*APAD + m] = v.x; As[(lc+1)*APAD + m] = v.y;
        As[(lc+2)*APAD + m] = v.z; As[(lc+3)*APAD + m] = v.w;
        *(float4*)(Bs + m*128 + lc) = *(const float4*)(W + m*FDIM + lc);
    }
    __syncthreads();
    int tx = tid & 15, ty = tid >> 4;
    u64 acc[8][4] = {};
    #pragma unroll 4
    for (int k = 0; k < 128; ++k) {
        float4 a0 = *(float4*)(As + k*APAD + (ty<<2));
        float4 a1 = *(float4*)(As + k*APAD + 64 + (ty<<2));
        ulonglong2 q0 = *(ulonglong2*)(Bs + k*128 + (tx<<2));
        ulonglong2 q1 = *(ulonglong2*)(Bs + k*128 + 64 + (tx<<2));
        u64 bu[4] = {q0.x, q0.y, q1.x, q1.y};
        float av[8] = {a0.x,a0.y,a0.z,a0.w,a1.x,a1.y,a1.z,a1.w};
        #pragma unroll
        for (int i = 0; i < 8; ++i) {
            u64 au = pack2(av[i]);
            #pragma unroll
            for (int j = 0; j < 4; ++j) ffma2(acc[i][j], au, bu[j]);
        }
    }
    #pragma unroll
    for (int i = 0; i < 8; ++i) {
        int row = (i < 4) ? ((ty<<2)+i) : (64+(ty<<2)+(i-4));
        float* cp = C + (m0 + row)*FDIM;
        float2 p0 = unpack2(acc[i][0]), p1 = unpack2(acc[i][1]);
        float2 p2 = unpack2(acc[i][2]), p3 = unpack2(acc[i][3]);
        float4 o0 = {p0.x,p0.y,p1.x,p1.y};
        float4 o1 = {p2.x,p2.y,p3.x,p3.y};
        *(float4*)(cp + (tx<<2)) = o0;
        *(float4*)(cp + 64 + (tx<<2)) = o1;
    }
}

// ---------------- GCN aggregation (combined node space) ----------------
__global__ void agg_kernel(const float* __restrict__ h, const float* __restrict__ bias,
                           const int* __restrict__ rp, const int* __restrict__ csrc,
                           const float* __restrict__ cw, const float* __restrict__ dinv,
                           float* __restrict__ out) {
    int n = blockIdx.x;
    int f = threadIdx.x;
    float di = dinv[n];
    float acc = fmaf(h[((size_t)n << 7) + f], di*di, bias[f]);
    int e = rp[n], e1 = rp[n+1];
    for (; e + 4 <= e1; e += 4) {
        int s0 = csrc[e], s1 = csrc[e+1], s2 = csrc[e+2], s3 = csrc[e+3];
        float w0 = cw[e], w1 = cw[e+1], w2 = cw[e+2], w3 = cw[e+3];
        acc = fmaf(h[((size_t)s0<<7)+f], w0, acc);
        acc = fmaf(h[((size_t)s1<<7)+f], w1, acc);
        acc = fmaf(h[((size_t)s2<<7)+f], w2, acc);
        acc = fmaf(h[((size_t)s3<<7)+f], w3, acc);
    }
    for (; e < e1; ++e)
        acc = fmaf(h[((size_t)csrc[e]<<7)+f], cw[e], acc);
    out[((size_t)n << 7) + f] = acc;
}

// ---------------- fused affinity (Xa@Aaff@Xb^T) + 2-anchor Sinkhorn ----------------
// blockIdx 0..255 -> sim1 (feat), 256..511 -> sim2 (fc)
__global__ void __launch_bounds__(256, 1)
aff_sink_kernel(const float* __restrict__ feat, const float* __restrict__ fc,
                const float* __restrict__ Aaff, const int* __restrict__ topk,
                float* __restrict__ sim1, float* __restrict__ sim2) {
    extern __shared__ float sm[];
    float* As = sm;                       // Xa^T then T^T : [128][APAD]
    float* Ws = sm + 128*APAD;            // Aaff: [128][128] (Ws[k][g] = Aaff[k][g])
    float* Bs = Ws + 128*128;             // Xb^T: [128][APAD]
    __shared__ float rmn[8], rmx[8], rbuf[8], bc[2];

    int tid = threadIdx.x;
    int lane = tid & 31, wid = tid >> 5;
    int which = blockIdx.x >> 8;
    int b = blockIdx.x & 255;
    const float* base = which ? fc : feat;
    const float* Xa = base + (size_t)b * LMAT;
    const float* Xb = base + HALF + (size_t)b * LMAT;
    float* P = (which ? sim2 : sim1) + (size_t)b * LMAT;

    int lr = tid >> 5, lc = (tid & 31) << 2;
    #pragma unroll
    for (int it = 0; it < 16; ++it) {
        int m = (it << 3) + lr;
        float4 va = *(const float4*)(Xa + m*128 + lc);
        As[(lc+0)*APAD + m] = va.x; As[(lc+1)*APAD + m] = va.y;
        As[(lc+2)*APAD + m] = va.z; As[(lc+3)*APAD + m] = va.w;
        float4 vb = *(const float4*)(Xb + m*128 + lc);
        Bs[(lc+0)*APAD + m] = vb.x; Bs[(lc+1)*APAD + m] = vb.y;
        Bs[(lc+2)*APAD + m] = vb.z; Bs[(lc+3)*APAD + m] = vb.w;
        *(float4*)(Ws + m*128 + lc) = *(const float4*)(Aaff + m*FDIM + lc);
    }
    __syncthreads();
    int tx = tid & 15, ty = tid >> 4;

    // loop 1: T = Xa @ Aaff
    u64 acc[8][4] = {};
    #pragma unroll 4
    for (int k = 0; k < 128; ++k) {
        float4 a0 = *(float4*)(As + k*APAD + (ty<<2));
        float4 a1 = *(float4*)(As + k*APAD + 64 + (ty<<2));
        ulonglong2 q0 = *(ulonglong2*)(Ws + k*128 + (tx<<2));
        ulonglong2 q1 = *(ulonglong2*)(Ws + k*128 + 64 + (tx<<2));
        u64 bu[4] = {q0.x, q0.y, q1.x, q1.y};
        float av[8] = {a0.x,a0.y,a0.z,a0.w,a1.x,a1.y,a1.z,a1.w};
        #pragma unroll
        for (int i = 0; i < 8; ++i) {
            u64 au = pack2(av[i]);
            #pragma unroll
            for (int j = 0; j < 4; ++j) ffma2(acc[i][j], au, bu[j]);
        }
    }
    __syncthreads();
    // write T^T into As: As[g][m] = T[m][g]
    #pragma unroll
    for (int i = 0; i < 8; ++i) {
        int row = (i < 4) ? ((ty<<2)+i) : (64+(ty<<2)+(i-4));
        #pragma unroll
        for (int jj = 0; jj < 4; ++jj) {
            int c0 = ((jj < 2) ? 0 : 64) + (tx<<2) + 2*(jj & 1);
            float2 p = unpack2(acc[i][jj]);
            As[(c0+0)*APAD + row] = p.x;
            As[(c0+1)*APAD + row] = p.y;
        }
    }
    __syncthreads();

    // loop 2: C = T @ Xb^T
    #pragma unroll
    for (int i = 0; i < 8; ++i)
        #pragma unroll
        for (int j = 0; j < 4; ++j) acc[i][j] = 0ull;
    #pragma unroll 4
    for (int k = 0; k < 128; ++k) {
        float4 a0 = *(float4*)(As + k*APAD + (ty<<2));
        float4 a1 = *(float4*)(As + k*APAD + 64 + (ty<<2));
        ulonglong2 q0 = *(ulonglong2*)(Bs + k*APAD + (tx<<2));
        ulonglong2 q1 = *(ulonglong2*)(Bs + k*APAD + 64 + (tx<<2));
        u64 bu[4] = {q0.x, q0.y, q1.x, q1.y};
        float av[8] = {a0.x,a0.y,a0.z,a0.w,a1.x,a1.y,a1.z,a1.w};
        #pragma unroll
        for (int i = 0; i < 8; ++i) {
            u64 au = pack2(av[i]);
            #pragma unroll
            for (int j = 0; j < 4; ++j) ffma2(acc[i][j], au, bu[j]);
        }
    }

    // unpack to za, track min/max
    float za[64];
    float mn = 3.4e38f, mx = -3.4e38f;
    #pragma unroll
    for (int i = 0; i < 8; ++i)
        #pragma unroll
        for (int jj = 0; jj < 4; ++jj) {
            float2 p = unpack2(acc[i][jj]);
            za[i*8 + jj*2 + 0] = p.x;
            za[i*8 + jj*2 + 1] = p.y;
            mn = fminf(mn, fminf(p.x, p.y));
            mx = fmaxf(mx, fmaxf(p.x, p.y));
        }
    #pragma unroll
    for (int off = 16; off; off >>= 1) {
        mn = fminf(mn, __shfl_xor_sync(0xffffffffu, mn, off));
        mx = fmaxf(mx, __shfl_xor_sync(0xffffffffu, mx, off));
    }
    if (lane == 0) { rmn[wid] = mn; rmx[wid] = mx; }
    __syncthreads();
    if (tid == 0) {
        float m1 = rmn[0], m2 = rmx[0];
        for (int w = 1; w < 8; ++w) { m1 = fminf(m1, rmn[w]); m2 = fmaxf(m2, rmx[w]); }
        bc[0] = m1 + m2;
    }
    __syncthreads();
    float Cc = bc[0];
    #pragma unroll
    for (int l = 0; l < 64; ++l) za[l] = fmaf(2.0f, za[l], -Cc);

    float kf = 0.5f * (float)(*topk);
    const float Lf = (float)LMAT;
    float lk = logf(kf / (Lf - kf));
    float delta = 0.0f, scale = 0.0f;
    for (int it = 0; it < SK_ITERS; ++it) {
        float T = 0.0f;
        #pragma unroll
        for (int l = 0; l < 64; ++l) T += fast_sigmoid(za[l] + delta);
        #pragma unroll
        for (int off = 16; off; off >>= 1)
            T += __shfl_xor_sync(0xffffffffu, T, off);
        if (lane == 0) rbuf[wid] = T;
        __syncthreads();
        if (tid == 0) {
            float s = 0.0f;
            for (int w = 0; w < 8; ++w) s += rbuf[w];
            bc[1] = s;
        }
        __syncthreads();
        float Tall = bc[1];
        if (it < SK_ITERS - 1) delta += lk + logf((Lf - Tall) / Tall);
        else scale = kf / Tall;
        __syncthreads();
    }

    #pragma unroll
    for (int i = 0; i < 8; ++i) {
        int row = (i < 4) ? ((ty<<2)+i) : (64+(ty<<2)+(i-4));
        #pragma unroll
        for (int jj = 0; jj < 4; ++jj) {
            int c0 = ((jj < 2) ? 0 : 64) + (tx<<2) + 2*(jj & 1);
            float2 o;
            o.x = scale * fast_sigmoid(za[i*8 + jj*2 + 0] + delta);
            o.y = scale * fast_sigmoid(za[i*8 + jj*2 + 1] + delta);
            *(float2*)(P + row*128 + c0) = o;
        }
    }
}

// ---------------- graph features + scorer ----------------
__global__ void gf_kernel(const float* __restrict__ feat, const float* __restrict__ fa,
                          const float* __restrict__ fb, const float* __restrict__ fcv,
                          float* __restrict__ scores) {
    int b = blockIdx.x;
    int d = threadIdx.x;              // 512
    int which = d >> 7, f = d & 127;
    const float* p1 = (which==0?feat:which==1?fa:which==2?fb:fcv) + (((size_t)b*NNODE)<<7) + f;
    float s = 0.0f;
    #pragma unroll 4
    for (int n = 0; n < NNODE; ++n) s += p1[n<<7];
    scores[b*1024 + d] = s;
    const float* p2 = (which==0?feat:which==1?fa:which==2?fb:fcv) + HALF + (((size_t)b*NNODE)<<7) + f;
    float m = -3.4e38f;
    #pragma unroll 4
    for (int n = 0; n < NNODE; ++n) m = fmaxf(m, p2[n<<7]);
    scores[b*1024 + 512 + d] = m;
}

__global__ void score_kernel(const float* __restrict__ scores,
                             const float* __restrict__ W1, const float* __restrict__ b1,
                             const float* __restrict__ W2, const float* __restrict__ b2,
                             float* __restrict__ ged) {
    int b = blockIdx.x;
    int j = threadIdx.x;              // 64
    __shared__ float sv[1024];
    __shared__ float rr[2];
    for (int i = j; i < 1024; i += 64) sv[i] = scores[b*1024 + i];
    __syncthreads();
    float acc = b1[j];
    #pragma unroll 8
    for (int i = 0; i < 1024; ++i)
        acc = fmaf(sv[i], W1[i*64 + j], acc);
    float pv = fmaxf(acc, 0.0f) * W2[j];
    #pragma unroll
    for (int off = 16; off; off >>= 1)
        pv += __shfl_xor_sync(0xffffffffu, pv, off);
    if ((j & 31) == 0) rr[j >> 5] = pv;
    __syncthreads();
    if (j == 0) {
        float v = rr[0] + rr[1] + b2[0];
        ged[b] = 1.0f / (1.0f + expf(-v));
    }
}

extern "C" void kernel_launch(void* const* d_in, const int* in_sizes, int n_in,
                              void* d_out, int out_size) {
    const float* x1    = (const float*)d_in[0];
    const int*   cent1 = (const int*)d_in[1];
    const float* rw1   = (const float*)d_in[2];
    const int*   src1  = (const int*)d_in[3];
    const int*   dst1  = (const int*)d_in[4];
    const float* x2    = (const float*)d_in[5];
    const int*   cent2 = (const int*)d_in[6];
    const float* rw2   = (const float*)d_in[7];
    const int*   src2  = (const int*)d_in[8];
    const int*   dst2  = (const int*)d_in[9];
    const float* emb   = (const float*)d_in[10];
    const float* initW = (const float*)d_in[11];
    const float* initb = (const float*)d_in[12];
    const float* W1    = (const float*)d_in[13];
    const float* b1    = (const float*)d_in[14];
    const float* W2    = (const float*)d_in[15];
    const float* b2    = (const float*)d_in[16];
    const float* W3    = (const float*)d_in[17];
    const float* b3    = (const float*)d_in[18];
    const float* Aaff  = (const float*)d_in[19];
    const float* scW1  = (const float*)d_in[20];
    const float* scb1  = (const float*)d_in[21];
    const float* scW2  = (const float*)d_in[22];
    const float* scb2  = (const float*)d_in[23];
    const int*   topk  = (const int*)d_in[24];

    Scratch* S = nullptr;
    cudaGetSymbolAddress((void**)&S, g_scratch);

    float* out  = (float*)d_out;
    float* ged  = out;
    float* sim1 = out + BATCH;
    float* sim2 = out + BATCH + (size_t)BATCH * LMAT;

    cudaFuncSetAttribute(gemm_aw_kernel,  cudaFuncAttributeMaxDynamicSharedMemorySize, SMEM_AW);
    cudaFuncSetAttribute(aff_sink_kernel, cudaFuncAttributeMaxDynamicSharedMemorySize, SMEM_FUSE);

    // CSR build (combined)
    cudaMemsetAsync(S->deg, 0, NTOT2*sizeof(int));
    cudaMemsetAsync(S->fill, 0, NTOT2*sizeof(int));
    count_kernel<<<NEDGE2/256, 256>>>(dst1, dst2, S->deg);
    dinv_kernel<<<NTOT2/256, 256>>>(S->deg, S->dinv);
    scan_block_kernel<<<64, 1024>>>(S->deg, S->rp, S->bsum);
    scan_top_kernel<<<1, 64>>>(S->bsum);
    scan_add_kernel<<<64, 1024>>>(S->rp, S->bsum);
    scatter_kernel<<<NEDGE2/256, 256>>>(src1, dst1, src2, dst2, S->rp, S->fill,
                                        S->dinv, S->csrc, S->cw);

    // Initial features (both graphs)
    init_feat_kernel<<<NTOT, 256>>>(x1, cent1, rw1, x2, cent2, rw2,
                                    emb, initW, initb, S->feat);

    // 3 GCN conv levels (both graphs at once)
    gemm_aw_kernel<<<NTOT2/128, 256, SMEM_AW>>>(S->feat, W1, S->htmp, 0);
    agg_kernel<<<NTOT2, 128>>>(S->htmp, b1, S->rp, S->csrc, S->cw, S->dinv, S->fa);
    gemm_aw_kernel<<<NTOT2/128, 256, SMEM_AW>>>(S->fa, W2, S->htmp, 1);
    agg_kernel<<<NTOT2, 128>>>(S->htmp, b2, S->rp, S->csrc, S->cw, S->dinv, S->fb);
    gemm_aw_kernel<<<NTOT2/128, 256, SMEM_AW>>>(S->fb, W3, S->htmp, 1);
    agg_kernel<<<NTOT2, 128>>>(S->htmp, b3, S->rp, S->csrc, S->cw, S->dinv, S->fc);

    // fused affinity + Sinkhorn for sim1 and sim2 in one launch
    aff_sink_kernel<<<2*BATCH, 256, SMEM_FUSE>>>(S->feat, S->fc, Aaff, topk, sim1, sim2);

    // graph features + scorer
    gf_kernel<<<BATCH, 512>>>(S->feat, S->fa, S->fb, S->fc, S->scores);
    score_kernel<<<BATCH, 64>>>(S->scores, scW1, scb1, scW2, scb2, ged);
}

// round 6
// speedup vs baseline: 1.3641x; 1.2061x over previous
#include <cuda_runtime.h>
#include <math.h>

#define BATCH   256
#define NNODE   128
#define NTOT    32768
#define NTOT2   65536
#define NEDGE   262144
#define NEDGE2  524288
#define FDIM    128
#define HALF    (NTOT*FDIM)
#define LDIMS   61
#define LMAT    16384
#define SK_ITERS 6
#define APAD    132
#define SMEM_AW   ((128*APAD + 128*128)*4)
#define SMEM_FUSE ((128*APAD + 128*128 + 128*APAD)*4)

typedef unsigned long long u64;

struct Scratch {
    float feat[NTOT2*FDIM];
    float fa[NTOT2*FDIM];
    float fb[NTOT2*FDIM];
    float fc[NTOT2*FDIM];
    float htmp[NTOT2*FDIM];
    float cw[NEDGE2];
    float dinv[NTOT2];
    float scores[BATCH*1024];
    int csrc[NEDGE2];
    int deg[NTOT2];
    int fill[NTOT2];
    int rp[NTOT2+1];
    int bsum[64];
};
__device__ Scratch g_scratch;

// ---------------- f32x2 packed FMA helpers ----------------
__device__ __forceinline__ u64 pack2(float v) {
    u64 r; asm("mov.b64 %0, {%1, %1};" : "=l"(r) : "f"(v)); return r;
}
__device__ __forceinline__ void ffma2(u64& d, u64 a, u64 b) {
    asm("fma.rn.f32x2 %0, %1, %2, %3;" : "=l"(d) : "l"(a), "l"(b), "l"(d));
}
__device__ __forceinline__ float2 unpack2(u64 v) {
    float2 f; asm("mov.b64 {%0, %1}, %2;" : "=f"(f.x), "=f"(f.y) : "l"(v)); return f;
}

// FMA-pipe sigmoid (no MUFU)
__device__ __forceinline__ float fast_sigmoid(float z) {
    float az = fminf(fabsf(z), 80.0f);
    float t = az * 1.4426950408889634f;
    float n = rintf(t);
    float w = -(t - n) * 0.6931471805599453f;
    float p = fmaf(w, 0.00833333377f, 0.0416666679f);
    p = fmaf(w, p, 0.16666667f);
    p = fmaf(w, p, 0.5f);
    p = fmaf(w, p, 1.0f);
    p = fmaf(w, p, 1.0f);
    float e = p * __int_as_float((127 - (int)n) << 23);
    float d = 1.0f + e;
    float y = fmaf(-0.5f, d, 1.45711f);
    y = y * fmaf(-d, y, 2.0f);
    y = y * fmaf(-d, y, 2.0f);
    y = y * fmaf(-d, y, 2.0f);
    return (z >= 0.0f) ? y : e * y;
}

// ---------------- CSR build ----------------
__global__ void zero_kernel(int* __restrict__ deg, int* __restrict__ fill) {
    int i = blockIdx.x*blockDim.x + threadIdx.x;     // NTOT2/4 int4s
    int4 z = {0,0,0,0};
    ((int4*)deg)[i] = z;
    ((int4*)fill)[i] = z;
}
__global__ void count_kernel(const int* __restrict__ dst1, const int* __restrict__ dst2,
                             int* __restrict__ deg) {
    int e = blockIdx.x*blockDim.x + threadIdx.x;
    if (e < NEDGE) atomicAdd(&deg[dst1[e]], 1);
    else if (e < NEDGE2) atomicAdd(&deg[dst2[e - NEDGE] + NTOT], 1);
}
__global__ void dinv_kernel(const int* __restrict__ deg, float* __restrict__ dinv) {
    int n = blockIdx.x*blockDim.x + threadIdx.x;
    if (n < NTOT2) dinv[n] = rsqrtf((float)(deg[n] + 1));
}
__global__ void scan_block_kernel(const int* __restrict__ deg, int* __restrict__ rp,
                                  int* __restrict__ bsum) {
    __shared__ int ws[32];
    int tid = threadIdx.x, lane = tid & 31, wid = tid >> 5;
    int gi = blockIdx.x*1024 + tid;
    int v = deg[gi];
    int x = v;
    #pragma unroll
    for (int off = 1; off < 32; off <<= 1) {
        int t = __shfl_up_sync(0xffffffffu, x, off);
        if (lane >= off) x += t;
    }
    if (lane == 31) ws[wid] = x;
    __syncthreads();
    if (wid == 0) {
        int y = ws[lane];
        #pragma unroll
        for (int off = 1; off < 32; off <<= 1) {
            int t = __shfl_up_sync(0xffffffffu, y, off);
            if (lane >= off) y += t;
        }
        ws[lane] = y;
    }
    __syncthreads();
    int woff = (wid > 0) ? ws[wid-1] : 0;
    rp[gi] = woff + x - v;
    if (tid == 1023) bsum[blockIdx.x] = woff + x;
}
// adds cross-block offsets; block-level prefix computed locally (removes a launch)
__global__ void scan_add_kernel(int* __restrict__ rp, const int* __restrict__ bsum) {
    __shared__ int off_s;
    if (threadIdx.x == 0) {
        int acc = 0;
        for (int i = 0; i < blockIdx.x; ++i) acc += bsum[i];
        off_s = acc;
    }
    __syncthreads();
    int gi = blockIdx.x*1024 + threadIdx.x;
    rp[gi] += off_s;
    if (gi == 0) rp[NTOT2] = NEDGE2;
}
__global__ void scatter_kernel(const int* __restrict__ src1, const int* __restrict__ dst1,
                               const int* __restrict__ src2, const int* __restrict__ dst2,
                               const int* __restrict__ rp, int* __restrict__ fill,
                               const float* __restrict__ dinv,
                               int* __restrict__ csrc, float* __restrict__ cw) {
    int e = blockIdx.x*blockDim.x + threadIdx.x;
    if (e >= NEDGE2) return;
    int s, d;
    if (e < NEDGE) { s = src1[e]; d = dst1[e]; }
    else { s = src2[e - NEDGE] + NTOT; d = dst2[e - NEDGE] + NTOT; }
    int pos = rp[d] + atomicAdd(&fill[d], 1);
    csrc[pos] = s;
    cw[pos] = dinv[s] * dinv[d];
}

// ---------------- initial features ----------------
__global__ void init_feat_kernel(const float* __restrict__ x1, const int* __restrict__ c1,
                                 const float* __restrict__ rw1,
                                 const float* __restrict__ x2, const int* __restrict__ c2,
                                 const float* __restrict__ rw2,
                                 const float* __restrict__ emb,
                                 const float* __restrict__ W, const float* __restrict__ bias,
                                 float* __restrict__ out) {
    int which = blockIdx.x >> 14;
    int bi = blockIdx.x & 16383;
    const float* x  = which ? x2 : x1;
    const int*   ce = which ? c2 : c1;
    const float* rw = which ? rw2 : rw1;
    int half = threadIdx.x >> 7;
    int f = threadIdx.x & 127;
    int node = bi*2 + half;
    __shared__ float a[2][LDIMS];
    if (f < 29)      a[half][f] = x[node*29 + f];
    else if (f < 45) a[half][f] = emb[ce[node]*16 + (f-29)];
    else if (f < 61) a[half][f] = rw[node*16 + (f-45)];
    __syncthreads();
    float acc = bias[f];
    #pragma unroll
    for (int c = 0; c < LDIMS; ++c)
        acc = fmaf(a[half][c], W[c*FDIM + f], acc);
    out[((size_t)(which*NTOT + node) << 7) + f] = fmaxf(acc, 0.0f);
}

// ---------------- GEMM C[M,128] = op(A)[M,128] @ W[128,128], f32x2 ----------------
__global__ void __launch_bounds__(256, 1)
gemm_aw_kernel(const float* __restrict__ A, const float* __restrict__ W,
               float* __restrict__ C, int relu_a) {
    extern __shared__ float sm[];
    float* As = sm;               // [128][APAD] transposed: As[k][m]
    float* Bs = sm + 128*APAD;    // [128][128]  Bs[k][n]
    int tid = threadIdx.x;
    size_t m0 = (size_t)blockIdx.x * 128;
    int lr = tid >> 5, lc = (tid & 31) << 2;
    #pragma unroll
    for (int it = 0; it < 16; ++it) {
        int m = (it << 3) + lr;
        float4 v = *(const float4*)(A + (m0 + m)*FDIM + lc);
        if (relu_a) { v.x=fmaxf(v.x,0.f); v.y=fmaxf(v.y,0.f); v.z=fmaxf(v.z,0.f); v.w=fmaxf(v.w,0.f); }
        As[(lc+0)*APAD + m] = v.x; As[(lc+1)*APAD + m] = v.y;
        As[(lc+2)*APAD + m] = v.z; As[(lc+3)*APAD + m] = v.w;
        *(float4*)(Bs + m*128 + lc) = *(const float4*)(W + m*FDIM + lc);
    }
    __syncthreads();
    int tx = tid & 15, ty = tid >> 4;
    u64 acc[8][4] = {};
    #pragma unroll 4
    for (int k = 0; k < 128; ++k) {
        float4 a0 = *(float4*)(As + k*APAD + (ty<<2));
        float4 a1 = *(float4*)(As + k*APAD + 64 + (ty<<2));
        ulonglong2 q0 = *(ulonglong2*)(Bs + k*128 + (tx<<2));
        ulonglong2 q1 = *(ulonglong2*)(Bs + k*128 + 64 + (tx<<2));
        u64 bu[4] = {q0.x, q0.y, q1.x, q1.y};
        float av[8] = {a0.x,a0.y,a0.z,a0.w,a1.x,a1.y,a1.z,a1.w};
        #pragma unroll
        for (int i = 0; i < 8; ++i) {
            u64 au = pack2(av[i]);
            #pragma unroll
            for (int j = 0; j < 4; ++j) ffma2(acc[i][j], au, bu[j]);
        }
    }
    #pragma unroll
    for (int i = 0; i < 8; ++i) {
        int row = (i < 4) ? ((ty<<2)+i) : (64+(ty<<2)+(i-4));
        float* cp = C + (m0 + row)*FDIM;
        float2 p0 = unpack2(acc[i][0]), p1 = unpack2(acc[i][1]);
        float2 p2 = unpack2(acc[i][2]), p3 = unpack2(acc[i][3]);
        float4 o0 = {p0.x,p0.y,p1.x,p1.y};
        float4 o1 = {p2.x,p2.y,p3.x,p3.y};
        *(float4*)(cp + (tx<<2)) = o0;
        *(float4*)(cp + 64 + (tx<<2)) = o1;
    }
}

// ---------------- GCN aggregation: warp per node, float4 per lane ----------------
__global__ void agg_kernel(const float* __restrict__ h, const float* __restrict__ bias,
                           const int* __restrict__ rp, const int* __restrict__ csrc,
                           const float* __restrict__ cw, const float* __restrict__ dinv,
                           float* __restrict__ out) {
    int n = (blockIdx.x << 3) + (threadIdx.x >> 5);   // 8 warps/block, 1 node/warp
    int lane = threadIdx.x & 31;
    const float4* h4 = (const float4*)h;
    float di = dinv[n];
    float4 bv = ((const float4*)bias)[lane];
    float4 hv = h4[((size_t)n << 5) + lane];
    float w2 = di*di;
    float4 acc;
    acc.x = fmaf(hv.x, w2, bv.x); acc.y = fmaf(hv.y, w2, bv.y);
    acc.z = fmaf(hv.z, w2, bv.z); acc.w = fmaf(hv.w, w2, bv.w);
    int e = rp[n], e1 = rp[n+1];
    for (; e + 4 <= e1; e += 4) {
        int s0 = csrc[e], s1 = csrc[e+1], s2 = csrc[e+2], s3 = csrc[e+3];
        float w0 = cw[e], w1 = cw[e+1], wv2 = cw[e+2], w3 = cw[e+3];
        float4 v0 = h4[((size_t)s0 << 5) + lane];
        float4 v1 = h4[((size_t)s1 << 5) + lane];
        float4 v2 = h4[((size_t)s2 << 5) + lane];
        float4 v3 = h4[((size_t)s3 << 5) + lane];
        acc.x = fmaf(v0.x, w0, acc.x); acc.y = fmaf(v0.y, w0, acc.y);
        acc.z = fmaf(v0.z, w0, acc.z); acc.w = fmaf(v0.w, w0, acc.w);
        acc.x = fmaf(v1.x, w1, acc.x); acc.y = fmaf(v1.y, w1, acc.y);
        acc.z = fmaf(v1.z, w1, acc.z); acc.w = fmaf(v1.w, w1, acc.w);
        acc.x = fmaf(v2.x, wv2, acc.x); acc.y = fmaf(v2.y, wv2, acc.y);
        acc.z = fmaf(v2.z, wv2, acc.z); acc.w = fmaf(v2.w, wv2, acc.w);
        acc.x = fmaf(v3.x, w3, acc.x); acc.y = fmaf(v3.y, w3, acc.y);
        acc.z = fmaf(v3.z, w3, acc.z); acc.w = fmaf(v3.w, w3, acc.w);
    }
    for (; e < e1; ++e) {
        float w = cw[e];
        float4 v = h4[((size_t)csrc[e] << 5) + lane];
        acc.x = fmaf(v.x, w, acc.x); acc.y = fmaf(v.y, w, acc.y);
        acc.z = fmaf(v.z, w, acc.z); acc.w = fmaf(v.w, w, acc.w);
    }
    ((float4*)out)[((size_t)n << 5) + lane] = acc;
}

// ---------------- fused affinity + 2-anchor Sinkhorn ----------------
__global__ void __launch_bounds__(256, 1)
aff_sink_kernel(const float* __restrict__ feat, const float* __restrict__ fc,
                const float* __restrict__ Aaff, const int* __restrict__ topk,
                float* __restrict__ sim1, float* __restrict__ sim2) {
    extern __shared__ float sm[];
    float* As = sm;
    float* Ws = sm + 128*APAD;
    float* Bs = Ws + 128*128;
    __shared__ float rmn[8], rmx[8], rbuf[8], bc[2];

    int tid = threadIdx.x;
    int lane = tid & 31, wid = tid >> 5;
    int which = blockIdx.x >> 8;
    int b = blockIdx.x & 255;
    const float* base = which ? fc : feat;
    const float* Xa = base + (size_t)b * LMAT;
    const float* Xb = base + HALF + (size_t)b * LMAT;
    float* P = (which ? sim2 : sim1) + (size_t)b * LMAT;

    int lr = tid >> 5, lc = (tid & 31) << 2;
    #pragma unroll
    for (int it = 0; it < 16; ++it) {
        int m = (it << 3) + lr;
        float4 va = *(const float4*)(Xa + m*128 + lc);
        As[(lc+0)*APAD + m] = va.x; As[(lc+1)*APAD + m] = va.y;
        As[(lc+2)*APAD + m] = va.z; As[(lc+3)*APAD + m] = va.w;
        float4 vb = *(const float4*)(Xb + m*128 + lc);
        Bs[(lc+0)*APAD + m] = vb.x; Bs[(lc+1)*APAD + m] = vb.y;
        Bs[(lc+2)*APAD + m] = vb.z; Bs[(lc+3)*APAD + m] = vb.w;
        *(float4*)(Ws + m*128 + lc) = *(const float4*)(Aaff + m*FDIM + lc);
    }
    __syncthreads();
    int tx = tid & 15, ty = tid >> 4;

    u64 acc[8][4] = {};
    #pragma unroll 4
    for (int k = 0; k < 128; ++k) {
        float4 a0 = *(float4*)(As + k*APAD + (ty<<2));
        float4 a1 = *(float4*)(As + k*APAD + 64 + (ty<<2));
        ulonglong2 q0 = *(ulonglong2*)(Ws + k*128 + (tx<<2));
        ulonglong2 q1 = *(ulonglong2*)(Ws + k*128 + 64 + (tx<<2));
        u64 bu[4] = {q0.x, q0.y, q1.x, q1.y};
        float av[8] = {a0.x,a0.y,a0.z,a0.w,a1.x,a1.y,a1.z,a1.w};
        #pragma unroll
        for (int i = 0; i < 8; ++i) {
            u64 au = pack2(av[i]);
            #pragma unroll
            for (int j = 0; j < 4; ++j) ffma2(acc[i][j], au, bu[j]);
        }
    }
    __syncthreads();
    #pragma unroll
    for (int i = 0; i < 8; ++i) {
        int row = (i < 4) ? ((ty<<2)+i) : (64+(ty<<2)+(i-4));
        #pragma unroll
        for (int jj = 0; jj < 4; ++jj) {
            int c0 = ((jj < 2) ? 0 : 64) + (tx<<2) + 2*(jj & 1);
            float2 p = unpack2(acc[i][jj]);
            As[(c0+0)*APAD + row] = p.x;
            As[(c0+1)*APAD + row] = p.y;
        }
    }
    __syncthreads();

    #pragma unroll
    for (int i = 0; i < 8; ++i)
        #pragma unroll
        for (int j = 0; j < 4; ++j) acc[i][j] = 0ull;
    #pragma unroll 4
    for (int k = 0; k < 128; ++k) {
        float4 a0 = *(float4*)(As + k*APAD + (ty<<2));
        float4 a1 = *(float4*)(As + k*APAD + 64 + (ty<<2));
        ulonglong2 q0 = *(ulonglong2*)(Bs + k*APAD + (tx<<2));
        ulonglong2 q1 = *(ulonglong2*)(Bs + k*APAD + 64 + (tx<<2));
        u64 bu[4] = {q0.x, q0.y, q1.x, q1.y};
        float av[8] = {a0.x,a0.y,a0.z,a0.w,a1.x,a1.y,a1.z,a1.w};
        #pragma unroll
        for (int i = 0; i < 8; ++i) {
            u64 au = pack2(av[i]);
            #pragma unroll
            for (int j = 0; j < 4; ++j) ffma2(acc[i][j], au, bu[j]);
        }
    }

    float za[64];
    float mn = 3.4e38f, mx = -3.4e38f;
    #pragma unroll
    for (int i = 0; i < 8; ++i)
        #pragma unroll
        for (int jj = 0; jj < 4; ++jj) {
            float2 p = unpack2(acc[i][jj]);
            za[i*8 + jj*2 + 0] = p.x;
            za[i*8 + jj*2 + 1] = p.y;
            mn = fminf(mn, fminf(p.x, p.y));
            mx = fmaxf(mx, fmaxf(p.x, p.y));
        }
    #pragma unroll
    for (int off = 16; off; off >>= 1) {
        mn = fminf(mn, __shfl_xor_sync(0xffffffffu, mn, off));
        mx = fmaxf(mx, __shfl_xor_sync(0xffffffffu, mx, off));
    }
    if (lane == 0) { rmn[wid] = mn; rmx[wid] = mx; }
    __syncthreads();
    if (tid == 0) {
        float m1 = rmn[0], m2 = rmx[0];
        for (int w = 1; w < 8; ++w) { m1 = fminf(m1, rmn[w]); m2 = fmaxf(m2, rmx[w]); }
        bc[0] = m1 + m2;
    }
    __syncthreads();
    float Cc = bc[0];
    #pragma unroll
    for (int l = 0; l < 64; ++l) za[l] = fmaf(2.0f, za[l], -Cc);

    float kf = 0.5f * (float)(*topk);
    const float Lf = (float)LMAT;
    float lk = logf(kf / (Lf - kf));
    float delta = 0.0f, scale = 0.0f;
    for (int it = 0; it < SK_ITERS; ++it) {
        float T = 0.0f;
        #pragma unroll
        for (int l = 0; l < 64; ++l) T += fast_sigmoid(za[l] + delta);
        #pragma unroll
        for (int off = 16; off; off >>= 1)
            T += __shfl_xor_sync(0xffffffffu, T, off);
        if (lane == 0) rbuf[wid] = T;
        __syncthreads();
        if (tid == 0) {
            float s = 0.0f;
            for (int w = 0; w < 8; ++w) s += rbuf[w];
            bc[1] = s;
        }
        __syncthreads();
        float Tall = bc[1];
        if (it < SK_ITERS - 1) delta += lk + logf((Lf - Tall) / Tall);
        else scale = kf / Tall;
        __syncthreads();
    }

    #pragma unroll
    for (int i = 0; i < 8; ++i) {
        int row = (i < 4) ? ((ty<<2)+i) : (64+(ty<<2)+(i-4));
        #pragma unroll
        for (int jj = 0; jj < 4; ++jj) {
            int c0 = ((jj < 2) ? 0 : 64) + (tx<<2) + 2*(jj & 1);
            float2 o;
            o.x = scale * fast_sigmoid(za[i*8 + jj*2 + 0] + delta);
            o.y = scale * fast_sigmoid(za[i*8 + jj*2 + 1] + delta);
            *(float2*)(P + row*128 + c0) = o;
        }
    }
}

// ---------------- graph features (warp per job, float4) + scorer ----------------
__global__ void gf_kernel(const float* __restrict__ feat, const float* __restrict__ fa,
                          const float* __restrict__ fb, const float* __restrict__ fcv,
                          float* __restrict__ scores) {
    int b = blockIdx.x;
    int tid = threadIdx.x;            // 256 = 8 warps
    int job = tid >> 5, lane = tid & 31;
    int buf = job & 3;
    const float* p = (buf==0?feat:buf==1?fa:buf==2?fb:fcv);
    if (job < 4) {
        const float4* p4 = (const float4*)(p + (((size_t)b*NNODE) << 7)) + lane;
        float4 s = {0,0,0,0};
        #pragma unroll 4
        for (int n = 0; n < NNODE; ++n) {
            float4 v = p4[n << 5];
            s.x += v.x; s.y += v.y; s.z += v.z; s.w += v.w;
        }
        ((float4*)(scores + b*1024 + buf*128))[lane] = s;
    } else {
        const float4* p4 = (const float4*)(p + HALF + (((size_t)b*NNODE) << 7)) + lane;
        float4 m = {-3.4e38f,-3.4e38f,-3.4e38f,-3.4e38f};
        #pragma unroll 4
        for (int n = 0; n < NNODE; ++n) {
            float4 v = p4[n << 5];
            m.x = fmaxf(m.x, v.x); m.y = fmaxf(m.y, v.y);
            m.z = fmaxf(m.z, v.z); m.w = fmaxf(m.w, v.w);
        }
        ((float4*)(scores + b*1024 + 512 + buf*128))[lane] = m;
    }
}

__global__ void score_kernel(const float* __restrict__ scores,
                             const float* __restrict__ W1, const float* __restrict__ b1,
                             const float* __restrict__ W2, const float* __restrict__ b2,
                             float* __restrict__ ged) {
    int b = blockIdx.x;
    int j = threadIdx.x;              // 64
    __shared__ float sv[1024];
    __shared__ float rr[2];
    for (int i = j; i < 1024; i += 64) sv[i] = scores[b*1024 + i];
    __syncthreads();
    float acc = b1[j];
    #pragma unroll 8
    for (int i = 0; i < 1024; ++i)
        acc = fmaf(sv[i], W1[i*64 + j], acc);
    float pv = fmaxf(acc, 0.0f) * W2[j];
    #pragma unroll
    for (int off = 16; off; off >>= 1)
        pv += __shfl_xor_sync(0xffffffffu, pv, off);
    if ((j & 31) == 0) rr[j >> 5] = pv;
    __syncthreads();
    if (j == 0) {
        float v = rr[0] + rr[1] + b2[0];
        ged[b] = 1.0f / (1.0f + expf(-v));
    }
}

extern "C" void kernel_launch(void* const* d_in, const int* in_sizes, int n_in,
                              void* d_out, int out_size) {
    const float* x1    = (const float*)d_in[0];
    const int*   cent1 = (const int*)d_in[1];
    const float* rw1   = (const float*)d_in[2];
    const int*   src1  = (const int*)d_in[3];
    const int*   dst1  = (const int*)d_in[4];
    const float* x2    = (const float*)d_in[5];
    const int*   cent2 = (const int*)d_in[6];
    const float* rw2   = (const float*)d_in[7];
    const int*   src2  = (const int*)d_in[8];
    const int*   dst2  = (const int*)d_in[9];
    const float* emb   = (const float*)d_in[10];
    const float* initW = (const float*)d_in[11];
    const float* initb = (const float*)d_in[12];
    const float* W1    = (const float*)d_in[13];
    const float* b1    = (const float*)d_in[14];
    const float* W2    = (const float*)d_in[15];
    const float* b2    = (const float*)d_in[16];
    const float* W3    = (const float*)d_in[17];
    const float* b3    = (const float*)d_in[18];
    const float* Aaff  = (const float*)d_in[19];
    const float* scW1  = (const float*)d_in[20];
    const float* scb1  = (const float*)d_in[21];
    const float* scW2  = (const float*)d_in[22];
    const float* scb2  = (const float*)d_in[23];
    const int*   topk  = (const int*)d_in[24];

    Scratch* S = nullptr;
    cudaGetSymbolAddress((void**)&S, g_scratch);

    float* out  = (float*)d_out;
    float* ged  = out;
    float* sim1 = out + BATCH;
    float* sim2 = out + BATCH + (size_t)BATCH * LMAT;

    cudaFuncSetAttribute(gemm_aw_kernel,  cudaFuncAttributeMaxDynamicSharedMemorySize, SMEM_AW);
    cudaFuncSetAttribute(aff_sink_kernel, cudaFuncAttributeMaxDynamicSharedMemorySize, SMEM_FUSE);

    // Launch order arranged so ncu (-s 5 -c 1) profiles gemm_aw #1 (launch #6).
    zero_kernel<<<NTOT2/4/256, 256>>>(S->deg, S->fill);                       // 1
    count_kernel<<<NEDGE2/256, 256>>>(dst1, dst2, S->deg);                    // 2
    init_feat_kernel<<<NTOT, 256>>>(x1, cent1, rw1, x2, cent2, rw2,
                                    emb, initW, initb, S->feat);              // 3
    dinv_kernel<<<NTOT2/256, 256>>>(S->deg, S->dinv);                         // 4
    scan_block_kernel<<<64, 1024>>>(S->deg, S->rp, S->bsum);                  // 5
    gemm_aw_kernel<<<NTOT2/128, 256, SMEM_AW>>>(S->feat, W1, S->htmp, 0);     // 6 <- profiled
    scan_add_kernel<<<64, 1024>>>(S->rp, S->bsum);                            // 7
    scatter_kernel<<<NEDGE2/256, 256>>>(src1, dst1, src2, dst2, S->rp, S->fill,
                                        S->dinv, S->csrc, S->cw);             // 8

    agg_kernel<<<NTOT2/8, 256>>>(S->htmp, b1, S->rp, S->csrc, S->cw, S->dinv, S->fa);
    gemm_aw_kernel<<<NTOT2/128, 256, SMEM_AW>>>(S->fa, W2, S->htmp, 1);
    agg_kernel<<<NTOT2/8, 256>>>(S->htmp, b2, S->rp, S->csrc, S->cw, S->dinv, S->fb);
    gemm_aw_kernel<<<NTOT2/128, 256, SMEM_AW>>>(S->fb, W3, S->htmp, 1);
    agg_kernel<<<NTOT2/8, 256>>>(S->htmp, b3, S->rp, S->csrc, S->cw, S->dinv, S->fc);

    aff_sink_kernel<<<2*BATCH, 256, SMEM_FUSE>>>(S->feat, S->fc, Aaff, topk, sim1, sim2);

    gf_kernel<<<BATCH, 256>>>(S->feat, S->fa, S->fb, S->fc, S->scores);
    score_kernel<<<BATCH, 64>>>(S->scores, scW1, scb1, scW2, scb2, ged);
}